// round 17
// baseline (speedup 1.0000x reference)
#include <cuda_runtime.h>
#include <stdint.h>
#include <math.h>

#define Bn 32
#define Sn 512
#define Hn 768
#define FDn 64
#define Pn 30
#define NROWS (Bn*Sn)    // 16384

typedef unsigned long long u64;

__device__ __forceinline__ void fma2(u64 &d, u64 a, u64 b) {
    asm("fma.rn.f32x2 %0, %1, %2, %0;" : "+l"(d) : "l"(a), "l"(b));
}
__device__ __forceinline__ u64 rep2(float a) {
    u64 r; asm("mov.b64 %0, {%1, %1};" : "=l"(r) : "f"(a)); return r;
}
__device__ __forceinline__ float2 unpk(u64 v) {
    float2 f; asm("mov.b64 {%0, %1}, %2;" : "=f"(f.x), "=f"(f.y) : "l"(v)); return f;
}
__device__ __forceinline__ void lds_v2b64(u64 &a, u64 &b, unsigned addr) {
    asm("ld.shared.v2.b64 {%0, %1}, [%2];" : "=l"(a), "=l"(b) : "r"(addr));
}

// ------------------ scratch ------------------
__device__ float g_WT [Hn * 32];          // W_t transposed [k][p], zero-padded p
__device__ float g_WaT[FDn * 32];         // W_a transposed [k][p]
__device__ float g_textT [Bn * 32 * Sn];  // [b][p][s]
__device__ float g_audioT[Bn * 32 * Sn];  // [b][p][s]
__device__ float g_part[256];
__device__ float g_raw0[Bn * Sn];
__device__ float g_prob[Bn * Sn];
__device__ float g_avp[Bn * 16 * Hn];
__device__ float g_h[Bn * Hn];

// ------------------ K0a/K0b/K0c: transpose weights ------------------
__global__ void k_prep_t0(const float* __restrict__ Wt) {
    int e = blockIdx.x * 256 + threadIdx.x;      // first 12288
    int p = e & 31, k = e >> 5;
    g_WT[e] = (p < Pn) ? Wt[p * Hn + k] : 0.f;
}
__global__ void k_prep_t1(const float* __restrict__ Wt) {
    int e = 12288 + blockIdx.x * 256 + threadIdx.x;   // second 12288
    int p = e & 31, k = e >> 5;
    g_WT[e] = (p < Pn) ? Wt[p * Hn + k] : 0.f;
}
__global__ void k_prep_a(const float* __restrict__ Wa) {
    int e = blockIdx.x * 256 + threadIdx.x;      // 2048
    int p = e & 31, k = e >> 5;
    g_WaT[e] = (p < Pn) ? Wa[p * FDn + k] : 0.f;
}

// ------------------ K1: projection, W fully smem-resident, barrier-free mainloop ------------------
// grid 256 (64-row tiles), block 256. Thread: 1 row (rthr=tid>>2), 8 p (pthr=tid&3).
#define SM_W_FLOATS (Hn * 32)                    // 24576
#define SM_A_FLOATS (FDn * 32)                   // 2048
#define SM_BYTES ((SM_W_FLOATS + SM_A_FLOATS) * 4)   // 106496 bytes

__global__ __launch_bounds__(256) void k_proj(const float* __restrict__ hs,
                                              const float* __restrict__ ad) {
    extern __shared__ __align__(16) float sm[];
    int tid = threadIdx.x;
    int pthr = tid & 3, rthr = tid >> 2;         // rthr 0..63
    int row0 = blockIdx.x * 64;
    int row = row0 + rthr;
    int b = row0 >> 9, s0 = row0 & 511;

    // ---- load full W_t^T + W_a^T into smem (coalesced, conflict-free) ----
    float4* s4 = (float4*)sm;
    const float4* w4 = (const float4*)g_WT;
    #pragma unroll
    for (int q = 0; q < 24; q++) s4[tid + 256 * q] = w4[tid + 256 * q];
    const float4* wa4 = (const float4*)g_WaT;
    #pragma unroll
    for (int q = 0; q < 2; q++)
        s4[(SM_W_FLOATS >> 2) + tid + 256 * q] = wa4[tid + 256 * q];
    __syncthreads();

    unsigned sbase = (unsigned)__cvta_generic_to_shared(sm);
    unsigned wb  = sbase + (unsigned)(pthr * 32);
    unsigned wba = sbase + (unsigned)(SM_W_FLOATS * 4) + (unsigned)(pthr * 32);

    // ---- text: stream own A row from gmem, no barriers ----
    const float4* arow = (const float4*)hs + (size_t)row * 192;
    u64 acc[4] = {0ull, 0ull, 0ull, 0ull};
    for (int c = 0; c < 192; c += 8) {
        float4 av[8];
        #pragma unroll
        for (int j = 0; j < 8; j++) av[j] = arow[c + j];
        #pragma unroll
        for (int j = 0; j < 8; j++) {
            int k0 = (c + j) * 4;
            #pragma unroll
            for (int kk = 0; kk < 4; kk++) {
                u64 w0, w1, w2, w3;
                lds_v2b64(w0, w1, wb + (unsigned)((k0 + kk) * 128));
                lds_v2b64(w2, w3, wb + (unsigned)((k0 + kk) * 128 + 16));
                float a = (kk == 0) ? av[j].x : (kk == 1) ? av[j].y :
                          (kk == 2) ? av[j].z : av[j].w;
                u64 r = rep2(a);
                fma2(acc[0], r, w0); fma2(acc[1], r, w1);
                fma2(acc[2], r, w2); fma2(acc[3], r, w3);
            }
        }
    }

    // ---- audio ----
    const float4* brow = (const float4*)ad + (size_t)row * 16;
    u64 aacc[4] = {0ull, 0ull, 0ull, 0ull};
    for (int c = 0; c < 16; c += 8) {
        float4 av[8];
        #pragma unroll
        for (int j = 0; j < 8; j++) av[j] = brow[c + j];
        #pragma unroll
        for (int j = 0; j < 8; j++) {
            int k0 = (c + j) * 4;
            #pragma unroll
            for (int kk = 0; kk < 4; kk++) {
                u64 w0, w1, w2, w3;
                lds_v2b64(w0, w1, wba + (unsigned)((k0 + kk) * 128));
                lds_v2b64(w2, w3, wba + (unsigned)((k0 + kk) * 128 + 16));
                float a = (kk == 0) ? av[j].x : (kk == 1) ? av[j].y :
                          (kk == 2) ? av[j].z : av[j].w;
                u64 r = rep2(a);
                fma2(aacc[0], r, w0); fma2(aacc[1], r, w1);
                fma2(aacc[2], r, w2); fma2(aacc[3], r, w3);
            }
        }
    }

    // ---- epilogue: stage through smem (W no longer needed), coalesced stores ----
    __syncthreads();                       // all W reads done
    float* sT  = sm;                       // 32 x 65
    float* sAu = sm + 2112;                // 32 x 65
    float* red = sm + 4224;                // 256
    float sumsq = 0.f;
    #pragma unroll
    for (int j = 0; j < 4; j++) {
        float2 f = unpk(acc[j]);
        sumsq += f.x * f.x + f.y * f.y;
        int p = pthr * 8 + 2 * j;
        sT[p * 65 + rthr]       = f.x;
        sT[(p + 1) * 65 + rthr] = f.y;
        float2 g = unpk(aacc[j]);
        sAu[p * 65 + rthr]       = g.x;
        sAu[(p + 1) * 65 + rthr] = g.y;
    }
    red[tid] = sumsq;
    __syncthreads();
    #pragma unroll
    for (int q = 0; q < 8; q++) {
        int e = tid + 256 * q;             // 2048
        int p = e >> 6, ss = e & 63;
        g_textT [((size_t)(b * 32 + p)) * 512 + s0 + ss] = sT[p * 65 + ss];
        g_audioT[((size_t)(b * 32 + p)) * 512 + s0 + ss] = sAu[p * 65 + ss];
    }
    for (int st = 128; st > 0; st >>= 1) {
        if (tid < st) red[tid] += red[tid + st];
        __syncthreads();
    }
    if (tid == 0) g_part[blockIdx.x] = red[0];
}

// ------------------ K3: symmetric score matrices (+ norm prologue) ------------------
__global__ __launch_bounds__(256) void k_scores(const float* __restrict__ twp,
                                                const float* __restrict__ awp,
                                                const float* __restrict__ fbp,
                                                float* __restrict__ out_ta,
                                                float* __restrict__ out_fa) {
    __shared__ float sTs[32 * 64], sTt[32 * 64], sAs[32 * 64], sAt[32 * 64];
    __shared__ float scs;
    int x = blockIdx.x, si = 0;
    while (x >= 8 - si) { x -= 8 - si; si++; }
    int ti = si + x;
    int b = blockIdx.y;
    int s0 = si * 64, t0 = ti * 64;
    int tid = threadIdx.x;

    if (tid < 32) {
        float v = 0.f;
        #pragma unroll
        for (int j = 0; j < 8; j++) v += g_part[tid + 32 * j];
        #pragma unroll
        for (int o = 16; o > 0; o >>= 1) v += __shfl_xor_sync(0xffffffff, v, o);
        if (tid == 0) scs = rsqrtf(v);
    }

    const float4* gT = (const float4*)(g_textT  + (size_t)b * 32 * 512);
    const float4* gA = (const float4*)(g_audioT + (size_t)b * 32 * 512);
    #pragma unroll
    for (int q = 0; q < 2; q++) {
        int e = tid + 256 * q;
        int p = e >> 4, c = e & 15;
        *(float4*)&sTs[p * 64 + c * 4] = gT[p * 128 + (s0 >> 2) + c];
        *(float4*)&sTt[p * 64 + c * 4] = gT[p * 128 + (t0 >> 2) + c];
        *(float4*)&sAs[p * 64 + c * 4] = gA[p * 128 + (s0 >> 2) + c];
        *(float4*)&sAt[p * 64 + c * 4] = gA[p * 128 + (t0 >> 2) + c];
    }
    __syncthreads();

    int tx = tid & 15, ty = tid >> 4;
    float st[16], sa[16];
    #pragma unroll
    for (int i = 0; i < 16; i++) { st[i] = 0.f; sa[i] = 0.f; }

    #pragma unroll 6
    for (int p = 0; p < Pn; p++) {
        float4 a = *(float4*)&sTs[p * 64 + ty * 4];
        float4 bt = *(float4*)&sTt[p * 64 + tx * 4];
        float4 c = *(float4*)&sAs[p * 64 + ty * 4];
        float4 d = *(float4*)&sAt[p * 64 + tx * 4];
        st[0]  += a.x*bt.x; st[1]  += a.x*bt.y; st[2]  += a.x*bt.z; st[3]  += a.x*bt.w;
        st[4]  += a.y*bt.x; st[5]  += a.y*bt.y; st[6]  += a.y*bt.z; st[7]  += a.y*bt.w;
        st[8]  += a.z*bt.x; st[9]  += a.z*bt.y; st[10] += a.z*bt.z; st[11] += a.z*bt.w;
        st[12] += a.w*bt.x; st[13] += a.w*bt.y; st[14] += a.w*bt.z; st[15] += a.w*bt.w;
        sa[0]  += c.x*d.x;  sa[1]  += c.x*d.y;  sa[2]  += c.x*d.z;  sa[3]  += c.x*d.w;
        sa[4]  += c.y*d.x;  sa[5]  += c.y*d.y;  sa[6]  += c.y*d.z;  sa[7]  += c.y*d.w;
        sa[8]  += c.z*d.x;  sa[9]  += c.z*d.y;  sa[10] += c.z*d.z;  sa[11] += c.z*d.w;
        sa[12] += c.w*d.x;  sa[13] += c.w*d.y;  sa[14] += c.w*d.z;  sa[15] += c.w*d.w;
    }

    float cs = scs;
    float tw = twp[0], aw = awp[0], fb = fbp[0];
    float ta[16], fa[16];
    float rw[4];
    #pragma unroll
    for (int i = 0; i < 4; i++)
        #pragma unroll
        for (int j = 0; j < 4; j++) {
            float t_ = fmaxf(st[i * 4 + j] * cs, 0.f);
            float a_ = fmaxf(sa[i * 4 + j], 0.f);
            float r_ = tw * t_ + aw * a_ + fb;
            ta[i * 4 + j] = t_;
            fa[i * 4 + j] = fmaxf(r_, 0.f);
            if (i == 0) rw[j] = r_;
        }

    #pragma unroll
    for (int i = 0; i < 4; i++) {
        int s = s0 + ty * 4 + i;
        size_t base = ((size_t)(b * Sn + s)) * Sn + t0 + tx * 4;
        *(float4*)(out_ta + base) = make_float4(ta[i*4], ta[i*4+1], ta[i*4+2], ta[i*4+3]);
        *(float4*)(out_fa + base) = make_float4(fa[i*4], fa[i*4+1], fa[i*4+2], fa[i*4+3]);
    }
    if (si == 0 && ty == 0)
        *(float4*)(g_raw0 + b * Sn + t0 + tx * 4) =
            make_float4(rw[0], rw[1], rw[2], rw[3]);

    if (si != ti) {
        #pragma unroll
        for (int j = 0; j < 4; j++) {
            int t = t0 + tx * 4 + j;
            size_t base = ((size_t)(b * Sn + t)) * Sn + s0 + ty * 4;
            *(float4*)(out_ta + base) = make_float4(ta[j], ta[4+j], ta[8+j], ta[12+j]);
            *(float4*)(out_fa + base) = make_float4(fa[j], fa[4+j], fa[8+j], fa[12+j]);
        }
    }
}

// ------------------ K4: softmax probs for s=0 row ------------------
__global__ __launch_bounds__(256) void k_soft(const float* __restrict__ am) {
    __shared__ float red[256];
    int b = blockIdx.x, tid = threadIdx.x;
    float mbase = am[b * Sn];
    float l0 = g_raw0[b * Sn + tid]       + am[b * Sn + tid]       + mbase;
    float l1 = g_raw0[b * Sn + tid + 256] + am[b * Sn + tid + 256] + mbase;

    red[tid] = fmaxf(l0, l1);
    __syncthreads();
    for (int s = 128; s > 0; s >>= 1) {
        if (tid < s) red[tid] = fmaxf(red[tid], red[tid + s]);
        __syncthreads();
    }
    float mx = red[0];
    __syncthreads();
    float e0 = expf(l0 - mx), e1 = expf(l1 - mx);
    red[tid] = e0 + e1;
    __syncthreads();
    for (int s = 128; s > 0; s >>= 1) {
        if (tid < s) red[tid] += red[tid + s];
        __syncthreads();
    }
    float inv = 1.f / red[0];
    g_prob[b * Sn + tid]       = e0 * inv;
    g_prob[b * Sn + tid + 256] = e1 * inv;
}

// ------------------ K5: att @ hidden ------------------
__global__ __launch_bounds__(192) void k_av(const float* __restrict__ hs) {
    __shared__ float sp[32];
    int b = blockIdx.x, cy = blockIdx.y, tid = threadIdx.x;
    int t0 = cy * 32;
    if (tid < 32) sp[tid] = g_prob[b * Sn + t0 + tid];
    __syncthreads();

    const float4* hb = (const float4*)(hs + (size_t)b * Sn * Hn);
    float4 acc = make_float4(0.f, 0.f, 0.f, 0.f);
    #pragma unroll 4
    for (int t = 0; t < 32; t++) {
        float p = sp[t];
        float4 h = hb[(size_t)(t0 + t) * 192 + tid];
        acc.x += p * h.x; acc.y += p * h.y; acc.z += p * h.z; acc.w += p * h.w;
    }
    ((float4*)g_avp)[(size_t)(b * 16 + cy) * 192 + tid] = acc;
}

// ------------------ K6: dense GEMV ------------------
__global__ __launch_bounds__(256) void k_dense(const float* __restrict__ hs,
                                               const float* __restrict__ Wd,
                                               const float* __restrict__ bd) {
    __shared__ float sx[Hn];
    int b = blockIdx.x, oc = blockIdx.y, tid = threadIdx.x;
    int w = tid >> 5, lane = tid & 31;

    for (int i = tid; i < Hn; i += 256) {
        float v = hs[(size_t)b * Sn * Hn + i];
        #pragma unroll
        for (int c = 0; c < 16; c++) v += g_avp[(size_t)(b * 16 + c) * Hn + i];
        sx[i] = v;
    }
    __syncthreads();

    const float4* sx4 = (const float4*)sx;
    #pragma unroll
    for (int q = 0; q < 12; q++) {
        int o = oc * 96 + w * 12 + q;
        const float4* w4 = (const float4*)(Wd + (size_t)o * Hn);
        float acc = 0.f;
        #pragma unroll
        for (int c = 0; c < 6; c++) {
            float4 wv = w4[c * 32 + lane];
            float4 xv = sx4[c * 32 + lane];
            acc += wv.x * xv.x + wv.y * xv.y + wv.z * xv.z + wv.w * xv.w;
        }
        #pragma unroll
        for (int s = 16; s > 0; s >>= 1)
            acc += __shfl_down_sync(0xffffffff, acc, s);
        if (lane == 0) g_h[b * Hn + o] = acc + bd[o];
    }
}

// ------------------ K7: layernorm ------------------
__global__ __launch_bounds__(256) void k_ln(const float* __restrict__ lw,
                                            const float* __restrict__ lb,
                                            float* __restrict__ out0) {
    __shared__ float red[256];
    int b = blockIdx.x, tid = threadIdx.x;
    float hv[3];
    #pragma unroll
    for (int j = 0; j < 3; j++) hv[j] = g_h[b * Hn + tid + 256 * j];

    red[tid] = hv[0] + hv[1] + hv[2];
    __syncthreads();
    for (int s = 128; s > 0; s >>= 1) {
        if (tid < s) red[tid] += red[tid + s];
        __syncthreads();
    }
    float u = red[0] / (float)Hn;
    __syncthreads();
    float vs = 0.f;
    #pragma unroll
    for (int j = 0; j < 3; j++) { float d = hv[j] - u; vs += d * d; }
    red[tid] = vs;
    __syncthreads();
    for (int s = 128; s > 0; s >>= 1) {
        if (tid < s) red[tid] += red[tid + s];
        __syncthreads();
    }
    float rstd = rsqrtf(red[0] / (float)Hn + 1e-12f);
    #pragma unroll
    for (int j = 0; j < 3; j++) {
        int o = tid + 256 * j;
        out0[b * Hn + o] = lw[o] * (hv[j] - u) * rstd + lb[o];
    }
}

// ------------------ launch ------------------
extern "C" void kernel_launch(void* const* d_in, const int* in_sizes, int n_in,
                              void* d_out, int out_size) {
    const float* hs = (const float*)d_in[0];
    const float* ad = (const float*)d_in[1];
    const float* am = (const float*)d_in[2];
    const float* Wt = (const float*)d_in[3];
    const float* Wa = (const float*)d_in[4];
    const float* tw = (const float*)d_in[5];
    const float* aw = (const float*)d_in[6];
    const float* fb = (const float*)d_in[7];
    const float* Wd = (const float*)d_in[8];
    const float* bd = (const float*)d_in[9];
    const float* lw = (const float*)d_in[10];
    const float* lb = (const float*)d_in[11];

    float* out    = (float*)d_out;
    float* out_h0 = out;
    float* out_ta = out + Bn * Hn;
    float* out_fa = out + Bn * Hn + (size_t)Bn * Sn * Sn;

    cudaFuncSetAttribute(k_proj, cudaFuncAttributeMaxDynamicSharedMemorySize,
                         SM_BYTES);

    k_prep_t0<<<48, 256>>>(Wt);
    k_prep_t1<<<48, 256>>>(Wt);
    k_prep_a<<<8, 256>>>(Wa);
    k_proj<<<256, 256, SM_BYTES>>>(hs, ad);   // 4th launch -> gets profiled
    k_scores<<<dim3(36, 32), 256>>>(tw, aw, fb, out_ta, out_fa);
    k_soft<<<32, 256>>>(am);
    k_av<<<dim3(32, 16), 192>>>(hs);
    k_dense<<<dim3(32, 8), 256>>>(hs, Wd, bd);
    k_ln<<<32, 256>>>(lw, lb, out_h0);
}